// round 6
// baseline (speedup 1.0000x reference)
#include <cuda_runtime.h>
#include <cuda_bf16.h>

// ---------------- problem constants ----------------
#define BB      8
#define QL      16
#define NHAT    16
#define HDIM    64
#define HID     1024
#define PASTLEN 8192
#define TOTKV   8208            // PASTLEN + QL
#define NSPLIT  8
#define SPLITLEN (TOTKV / NSPLIT)   // 1026
#define CHUNK   128

// ---------------- device scratch (no allocation allowed) ----------------
__device__ float g_q  [BB*NHAT*QL*HDIM];                    // pre-scaled by 0.125
__device__ float g_k  [BB*NHAT*QL*HDIM];                    // new K rows
__device__ float g_v  [BB*NHAT*QL*HDIM];                    // new V rows
__device__ float g_part_acc[BB*NHAT*NSPLIT*QL*HDIM];        // unnormalized PV partials
__device__ float g_part_m  [BB*NHAT*NSPLIT*QL];
__device__ float g_part_l  [BB*NHAT*NSPLIT*QL];
__device__ float g_mid [BB*QL*HID];                         // permuted attn output

// ============================================================
// Kernel 1: fused QKV projection.
// C[m][n] = hidden[m][:] . W[n][:] + b[n], m in [0,128), n in [0,3072)
// 64x64 tile, 256 threads, 4x4 per thread.
// ============================================================
__global__ __launch_bounds__(256) void qkv_kernel(
    const float* __restrict__ A,
    const float* __restrict__ Wq, const float* __restrict__ bq,
    const float* __restrict__ Wk, const float* __restrict__ bk,
    const float* __restrict__ Wv, const float* __restrict__ bv)
{
    __shared__ float As[64][17];
    __shared__ float Ws[64][17];

    const int tid = threadIdx.x;
    const int tx = tid & 15, ty = tid >> 4;
    const int col0 = blockIdx.x * 64;       // 0..3071
    const int row0 = blockIdx.y * 64;       // 0 or 64
    const int mat  = col0 >> 10;            // 0=q 1=k 2=v
    const int f0   = col0 & 1023;

    const float* W    = (mat == 0) ? Wq : (mat == 1) ? Wk : Wv;
    const float* bias = (mat == 0) ? bq : (mat == 1) ? bk : bv;

    float acc[4][4];
#pragma unroll
    for (int r = 0; r < 4; r++)
#pragma unroll
        for (int c = 0; c < 4; c++) acc[r][c] = 0.f;

    const int lr = tid >> 2;         // 0..63
    const int lk = (tid & 3) * 4;    // 0,4,8,12

    for (int kt = 0; kt < HID; kt += 16) {
        float4 a4 = *(const float4*)&A[(size_t)(row0 + lr) * HID + kt + lk];
        float4 w4 = *(const float4*)&W[(size_t)(f0  + lr) * HID + kt + lk];
        As[lr][lk] = a4.x; As[lr][lk+1] = a4.y; As[lr][lk+2] = a4.z; As[lr][lk+3] = a4.w;
        Ws[lr][lk] = w4.x; Ws[lr][lk+1] = w4.y; Ws[lr][lk+2] = w4.z; Ws[lr][lk+3] = w4.w;
        __syncthreads();
#pragma unroll
        for (int kk = 0; kk < 16; kk++) {
            float av[4], wv[4];
#pragma unroll
            for (int r = 0; r < 4; r++) av[r] = As[ty*4 + r][kk];
#pragma unroll
            for (int c = 0; c < 4; c++) wv[c] = Ws[tx*4 + c][kk];
#pragma unroll
            for (int r = 0; r < 4; r++)
#pragma unroll
                for (int c = 0; c < 4; c++) acc[r][c] += av[r] * wv[c];
        }
        __syncthreads();
    }

#pragma unroll
    for (int r = 0; r < 4; r++) {
        const int m = row0 + ty*4 + r;
        const int b = m >> 4, iq = m & 15;
#pragma unroll
        for (int c = 0; c < 4; c++) {
            const int f = f0 + tx*4 + c;
            const int h = f >> 6, d = f & 63;
            float v = acc[r][c] + bias[f];
            const int dst = ((b*NHAT + h)*QL + iq)*HDIM + d;
            if (mat == 0)      g_q[dst] = v * 0.125f;   // 1/sqrt(64)
            else if (mat == 1) g_k[dst] = v;
            else               g_v[dst] = v;
        }
    }
}

// ============================================================
// Kernel 2: flash attention with split-KV.
// grid = BB*NHAT*NSPLIT, block = 256.
// Per chunk of 128 kv rows:
//   phase A: 2 threads per row compute half the dot products, shfl-combined.
//   phase B: 16-lane group per query row does online softmax + PV.
// ============================================================
__global__ __launch_bounds__(256) void attn_kernel(
    const float* __restrict__ past_k,
    const float* __restrict__ past_v,
    const float* __restrict__ padmask)
{
    __shared__ float4 qs4[QL*16];                    // 16 rows x 64 dims (4KB)
    __shared__ __align__(16) float S[QL*CHUNK];      // scores / probs (8KB)
    __shared__ float4 Vs4[CHUNK*16];                 // V chunk (32KB)

    const int t  = threadIdx.x;
    const int bh = blockIdx.x >> 3;
    const int sp = blockIdx.x & (NSPLIT - 1);
    const int b  = bh >> 4;
    const int s0 = sp * SPLITLEN, s1 = s0 + SPLITLEN;

    const float4* pk4 = (const float4*)past_k;
    const float4* pv4 = (const float4*)past_v;
    const float4* gk4 = (const float4*)g_k;
    const float4* gv4 = (const float4*)g_v;

    qs4[t] = ((const float4*)g_q)[bh*256 + t];

    const int i  = t >> 4, dg = t & 15;   // phase B ids
    const int rl = t >> 1, half = t & 1;  // phase A ids

    float m = -1e30f, l = 0.f;
    float4 acc = make_float4(0.f, 0.f, 0.f, 0.f);

    for (int c0 = s0; c0 < s1; c0 += CHUNK) {
        const int nrows = min(CHUNK, s1 - c0);
        __syncthreads();

        // ---- cooperative V load (coalesced; zero invalid rows) ----
#pragma unroll
        for (int it = 0; it < (CHUNK*16)/256; it++) {
            const int f = t + it*256;
            const int row = f >> 4, c = f & 15;
            const int gr = c0 + row;
            float4 val = make_float4(0.f, 0.f, 0.f, 0.f);
            if (row < nrows) {
                val = (gr < PASTLEN)
                    ? pv4[(size_t)(bh*PASTLEN + gr)*16 + c]
                    : gv4[(bh*QL + (gr - PASTLEN))*16 + c];
            }
            Vs4[f] = val;
        }

        // ---- phase A: scores ----
        float s[QL];
#pragma unroll
        for (int ii = 0; ii < QL; ii++) s[ii] = 0.f;
        const int j = c0 + rl;
        const bool valid = (rl < nrows);
        if (valid) {
            const float4* krow = (j < PASTLEN)
                ? pk4 + (size_t)(bh*PASTLEN + j)*16
                : gk4 + (size_t)(bh*QL + (j - PASTLEN))*16;
#pragma unroll
            for (int dbl = 0; dbl < 8; dbl++) {
                const int db = half*8 + dbl;
                const float4 k4 = krow[db];
#pragma unroll
                for (int ii = 0; ii < QL; ii++) {
                    const float4 q4 = qs4[ii*16 + db];
                    s[ii] += k4.x*q4.x + k4.y*q4.y + k4.z*q4.z + k4.w*q4.w;
                }
            }
        }
        float padadd = 0.f;
        if (valid && half == 0) padadd = padmask[b*TOTKV + j] * -1e9f;
#pragma unroll
        for (int ii = 0; ii < QL; ii++) {
            float stot = s[ii] + __shfl_xor_sync(0xffffffffu, s[ii], 1);
            if (half == 0) {
                if (!valid) stot = -1e30f;
                else {
                    stot += padadd;
                    if (j > PASTLEN + ii) stot -= 1e9f;
                }
                S[ii*CHUNK + rl] = stot;
            }
        }
        __syncthreads();

        // ---- phase B: online softmax + PV ----
        float mx = -1e30f;
#pragma unroll
        for (int jj = 0; jj < CHUNK/16; jj++)
            mx = fmaxf(mx, S[i*CHUNK + dg + jj*16]);
        mx = fmaxf(mx, __shfl_xor_sync(0xffffffffu, mx, 8));
        mx = fmaxf(mx, __shfl_xor_sync(0xffffffffu, mx, 4));
        mx = fmaxf(mx, __shfl_xor_sync(0xffffffffu, mx, 2));
        mx = fmaxf(mx, __shfl_xor_sync(0xffffffffu, mx, 1));

        const float mnew = fmaxf(m, mx);
        const float corr = __expf(m - mnew);
        float lsum = 0.f;
#pragma unroll
        for (int jj = 0; jj < CHUNK/16; jj++) {
            const int idx = i*CHUNK + dg + jj*16;
            const float p = __expf(S[idx] - mnew);
            S[idx] = p;
            lsum += p;
        }
        __syncwarp();
        lsum += __shfl_xor_sync(0xffffffffu, lsum, 8);
        lsum += __shfl_xor_sync(0xffffffffu, lsum, 4);
        lsum += __shfl_xor_sync(0xffffffffu, lsum, 2);
        lsum += __shfl_xor_sync(0xffffffffu, lsum, 1);
        l = l * corr + lsum;
        m = mnew;
        acc.x *= corr; acc.y *= corr; acc.z *= corr; acc.w *= corr;

        const float4* S4 = (const float4*)(S + i*CHUNK);
#pragma unroll 8
        for (int j4 = 0; j4 < CHUNK/4; j4++) {
            const float4 p4 = S4[j4];
            const float4 v0 = Vs4[(j4*4 + 0)*16 + dg];
            const float4 v1 = Vs4[(j4*4 + 1)*16 + dg];
            const float4 v2 = Vs4[(j4*4 + 2)*16 + dg];
            const float4 v3 = Vs4[(j4*4 + 3)*16 + dg];
            acc.x += p4.x*v0.x + p4.y*v1.x + p4.z*v2.x + p4.w*v3.x;
            acc.y += p4.x*v0.y + p4.y*v1.y + p4.z*v2.y + p4.w*v3.y;
            acc.z += p4.x*v0.z + p4.y*v1.z + p4.z*v2.z + p4.w*v3.z;
            acc.w += p4.x*v0.w + p4.y*v1.w + p4.z*v2.w + p4.w*v3.w;
        }
    }

    // ---- write split partials ----
    const int pb = blockIdx.x;               // bh*NSPLIT + sp
    ((float4*)g_part_acc)[(pb*QL + i)*16 + dg] = acc;
    if (dg == 0) {
        g_part_m[pb*QL + i] = m;
        g_part_l[pb*QL + i] = l;
    }
}

// ============================================================
// Kernel 3: combine splits, write permuted mid layout.
// out[b,h,i,d] -> mid[b][d>>2][(d&3)*256 + i*16 + h]
// ============================================================
__global__ __launch_bounds__(256) void combine_kernel()
{
    const int bh = blockIdx.x;
    const int b = bh >> 4, h = bh & 15;
    const int t = threadIdx.x;
    const int i = t >> 4, dg = t & 15;

    float mg = -1e30f;
#pragma unroll
    for (int sp = 0; sp < NSPLIT; sp++)
        mg = fmaxf(mg, g_part_m[(bh*NSPLIT + sp)*QL + i]);

    float L = 0.f;
    float4 acc = make_float4(0.f, 0.f, 0.f, 0.f);
#pragma unroll
    for (int sp = 0; sp < NSPLIT; sp++) {
        const int pi = (bh*NSPLIT + sp)*QL + i;
        const float w = __expf(g_part_m[pi] - mg);
        L += g_part_l[pi] * w;
        const float4 a = ((const float4*)g_part_acc)[pi*16 + dg];
        acc.x += a.x * w; acc.y += a.y * w; acc.z += a.z * w; acc.w += a.w * w;
    }
    const float inv = 1.f / L;
    const float v[4] = {acc.x*inv, acc.y*inv, acc.z*inv, acc.w*inv};
#pragma unroll
    for (int k = 0; k < 4; k++) {
        const int d = dg*4 + k;
        g_mid[b*(QL*HID) + (d >> 2)*HID + (d & 3)*256 + i*16 + h] = v[k];
    }
}

// ============================================================
// Kernel 4: output projection. out = mid @ Wo^T + bo
// ============================================================
__global__ __launch_bounds__(256) void oproj_kernel(
    const float* __restrict__ Wo, const float* __restrict__ bo,
    float* __restrict__ out)
{
    __shared__ float As[64][17];
    __shared__ float Ws[64][17];

    const int tid = threadIdx.x;
    const int tx = tid & 15, ty = tid >> 4;
    const int col0 = blockIdx.x * 64;
    const int row0 = blockIdx.y * 64;

    float acc[4][4];
#pragma unroll
    for (int r = 0; r < 4; r++)
#pragma unroll
        for (int c = 0; c < 4; c++) acc[r][c] = 0.f;

    const int lr = tid >> 2;
    const int lk = (tid & 3) * 4;

    for (int kt = 0; kt < HID; kt += 16) {
        float4 a4 = *(const float4*)&g_mid[(size_t)(row0 + lr) * HID + kt + lk];
        float4 w4 = *(const float4*)&Wo   [(size_t)(col0 + lr) * HID + kt + lk];
        As[lr][lk] = a4.x; As[lr][lk+1] = a4.y; As[lr][lk+2] = a4.z; As[lr][lk+3] = a4.w;
        Ws[lr][lk] = w4.x; Ws[lr][lk+1] = w4.y; Ws[lr][lk+2] = w4.z; Ws[lr][lk+3] = w4.w;
        __syncthreads();
#pragma unroll
        for (int kk = 0; kk < 16; kk++) {
            float av[4], wv[4];
#pragma unroll
            for (int r = 0; r < 4; r++) av[r] = As[ty*4 + r][kk];
#pragma unroll
            for (int c = 0; c < 4; c++) wv[c] = Ws[tx*4 + c][kk];
#pragma unroll
            for (int r = 0; r < 4; r++)
#pragma unroll
                for (int c = 0; c < 4; c++) acc[r][c] += av[r] * wv[c];
        }
        __syncthreads();
    }

#pragma unroll
    for (int r = 0; r < 4; r++) {
        const int mrow = row0 + ty*4 + r;
#pragma unroll
        for (int c = 0; c < 4; c++) {
            const int n = col0 + tx*4 + c;
            out[(size_t)mrow * HID + n] = acc[r][c] + bo[n];
        }
    }
}

// ============================================================
extern "C" void kernel_launch(void* const* d_in, const int* in_sizes, int n_in,
                              void* d_out, int out_size)
{
    const float* hidden  = (const float*)d_in[0];
    const float* past_k  = (const float*)d_in[1];
    const float* past_v  = (const float*)d_in[2];
    // d_in[3] causal_mask: computed analytically (j > PASTLEN + i)
    const float* padmask = (const float*)d_in[4];
    const float* Wq = (const float*)d_in[5];
    const float* bq = (const float*)d_in[6];
    const float* Wk = (const float*)d_in[7];
    const float* bk = (const float*)d_in[8];
    const float* Wv = (const float*)d_in[9];
    const float* bv = (const float*)d_in[10];
    const float* Wo = (const float*)d_in[11];
    const float* bo = (const float*)d_in[12];
    float* out = (float*)d_out;

    qkv_kernel<<<dim3(48, 2), 256>>>(hidden, Wq, bq, Wk, bk, Wv, bv);
    attn_kernel<<<BB*NHAT*NSPLIT, 256>>>(past_k, past_v, padmask);
    combine_kernel<<<BB*NHAT, 256>>>();
    oproj_kernel<<<dim3(16, 2), 256>>>(Wo, bo, out);
}

// round 8
// speedup vs baseline: 1.2178x; 1.2178x over previous
#include <cuda_runtime.h>
#include <cuda_bf16.h>

// ---------------- problem constants ----------------
#define BB      8
#define QL      16
#define NHAT    16
#define HDIM    64
#define HID     1024
#define PASTLEN 8192
#define TOTKV   8208            // PASTLEN + QL
#define NSPLIT  16
#define SPLITBASE 512           // 4 full chunks per split; split 15 takes +16 tail
#define CHUNK   128
#define KSPLIT  4
#define KSLICE  (HID / KSPLIT)  // 256

// ---------------- device scratch (no allocation allowed) ----------------
__device__ float g_q  [BB*NHAT*QL*HDIM];                    // pre-scaled by 0.125
__device__ float g_k  [BB*NHAT*QL*HDIM];                    // new K rows
__device__ float g_v  [BB*NHAT*QL*HDIM];                    // new V rows
__device__ float g_qkv_pp[KSPLIT*128*3072];                 // qkv split-K partials
__device__ float g_op_pp [KSPLIT*128*HID];                  // oproj split-K partials
__device__ float g_part_acc[BB*NHAT*NSPLIT*QL*HDIM];        // unnormalized PV partials
__device__ float g_part_m  [BB*NHAT*NSPLIT*QL];
__device__ float g_part_l  [BB*NHAT*NSPLIT*QL];
__device__ float g_mid [BB*QL*HID];                         // permuted attn output

// ============================================================
// Kernel 1a: fused QKV projection, split-K partial.
// grid (48, 2, KSPLIT), 256 thr, 64x64 tile, 4x4/thread,
// register-prefetched k-tiles.
// ============================================================
__global__ __launch_bounds__(256) void qkv_part_kernel(
    const float* __restrict__ A,
    const float* __restrict__ Wq, const float* __restrict__ Wk,
    const float* __restrict__ Wv)
{
    __shared__ float As[64][17];
    __shared__ float Ws[64][17];

    const int tid = threadIdx.x;
    const int tx = tid & 15, ty = tid >> 4;
    const int col0 = blockIdx.x * 64;       // 0..3071
    const int row0 = blockIdx.y * 64;
    const int ks   = blockIdx.z;
    const int mat  = col0 >> 10;            // 0=q 1=k 2=v
    const int f0   = col0 & 1023;
    const float* W = (mat == 0) ? Wq : (mat == 1) ? Wk : Wv;

    float acc[4][4];
#pragma unroll
    for (int r = 0; r < 4; r++)
#pragma unroll
        for (int c = 0; c < 4; c++) acc[r][c] = 0.f;

    const int lr = tid >> 2;         // 0..63
    const int lk = (tid & 3) * 4;    // 0,4,8,12
    const float* Arow = A + (size_t)(row0 + lr) * HID + ks*KSLICE + lk;
    const float* Wrow = W + (size_t)(f0  + lr) * HID + ks*KSLICE + lk;

    float4 a4 = *(const float4*)Arow;
    float4 w4 = *(const float4*)Wrow;

    for (int t = 0; t < KSLICE/16; t++) {
        As[lr][lk] = a4.x; As[lr][lk+1] = a4.y; As[lr][lk+2] = a4.z; As[lr][lk+3] = a4.w;
        Ws[lr][lk] = w4.x; Ws[lr][lk+1] = w4.y; Ws[lr][lk+2] = w4.z; Ws[lr][lk+3] = w4.w;
        __syncthreads();
        if (t < KSLICE/16 - 1) {                // prefetch next k-tile
            a4 = *(const float4*)(Arow + (t+1)*16);
            w4 = *(const float4*)(Wrow + (t+1)*16);
        }
#pragma unroll
        for (int kk = 0; kk < 16; kk++) {
            float av[4], wv[4];
#pragma unroll
            for (int r = 0; r < 4; r++) av[r] = As[ty*4 + r][kk];
#pragma unroll
            for (int c = 0; c < 4; c++) wv[c] = Ws[tx*4 + c][kk];
#pragma unroll
            for (int r = 0; r < 4; r++)
#pragma unroll
                for (int c = 0; c < 4; c++) acc[r][c] += av[r] * wv[c];
        }
        __syncthreads();
    }

#pragma unroll
    for (int r = 0; r < 4; r++) {
        const int m = row0 + ty*4 + r;
        float4 o = make_float4(acc[r][0], acc[r][1], acc[r][2], acc[r][3]);
        *(float4*)&g_qkv_pp[((size_t)ks*128 + m)*3072 + col0 + tx*4] = o;
    }
}

// ============================================================
// Kernel 1b: reduce qkv split-K partials, add bias, scatter to
// [b][h][i][d] layout. grid 384 x 256, one float4 per thread.
// ============================================================
__global__ __launch_bounds__(256) void qkv_reduce_kernel(
    const float* __restrict__ bq, const float* __restrict__ bk,
    const float* __restrict__ bv)
{
    const int idx = blockIdx.x * 256 + threadIdx.x;   // float4 index, 0..98303
    const int m = idx / 768;
    const int f = (idx - m*768) * 4;                  // 0..3068
    const size_t base = (size_t)m*3072 + f;

    float4 s = *(const float4*)&g_qkv_pp[base];
#pragma unroll
    for (int ks = 1; ks < KSPLIT; ks++) {
        float4 p = *(const float4*)&g_qkv_pp[(size_t)ks*128*3072 + base];
        s.x += p.x; s.y += p.y; s.z += p.z; s.w += p.w;
    }

    const int mat = f >> 10;
    const int fl  = f & 1023;
    const float* bias = (mat == 0) ? bq : (mat == 1) ? bk : bv;
    s.x += bias[fl]; s.y += bias[fl+1]; s.z += bias[fl+2]; s.w += bias[fl+3];

    const int b = m >> 4, iq = m & 15;
    const int h = fl >> 6, d = fl & 63;
    const int dst = ((b*NHAT + h)*QL + iq)*HDIM + d;
    if (mat == 0) {
        s.x *= 0.125f; s.y *= 0.125f; s.z *= 0.125f; s.w *= 0.125f;  // 1/sqrt(64)
        *(float4*)&g_q[dst] = s;
    } else if (mat == 1) {
        *(float4*)&g_k[dst] = s;
    } else {
        *(float4*)&g_v[dst] = s;
    }
}

// ============================================================
// Kernel 2: flash attention with split-KV (chunk-aligned splits).
// grid = BB*NHAT*NSPLIT, block = 256.
// ============================================================
__global__ __launch_bounds__(256) void attn_kernel(
    const float* __restrict__ past_k,
    const float* __restrict__ past_v,
    const float* __restrict__ padmask)
{
    __shared__ float4 qs4[QL*16];                    // 4KB
    __shared__ __align__(16) float S[QL*CHUNK];      // 8KB
    __shared__ float4 Vs4[CHUNK*16];                 // 32KB

    const int t  = threadIdx.x;
    const int bh = blockIdx.x >> 4;
    const int sp = blockIdx.x & (NSPLIT - 1);
    const int b  = bh >> 4;
    const int s0 = sp * SPLITBASE;
    const int s1 = (sp == NSPLIT-1) ? TOTKV : s0 + SPLITBASE;

    const float4* pk4 = (const float4*)past_k;
    const float4* pv4 = (const float4*)past_v;
    const float4* gk4 = (const float4*)g_k;
    const float4* gv4 = (const float4*)g_v;

    qs4[t] = ((const float4*)g_q)[bh*256 + t];

    const int i  = t >> 4, dg = t & 15;   // phase B ids
    const int rl = t >> 1, half = t & 1;  // phase A ids

    float m = -1e30f, l = 0.f;
    float4 acc = make_float4(0.f, 0.f, 0.f, 0.f);

    for (int c0 = s0; c0 < s1; c0 += CHUNK) {
        const int nrows = min(CHUNK, s1 - c0);
        __syncthreads();

        // ---- cooperative V load (coalesced; zero invalid rows) ----
#pragma unroll
        for (int it = 0; it < (CHUNK*16)/256; it++) {
            const int f = t + it*256;
            const int row = f >> 4, c = f & 15;
            const int gr = c0 + row;
            float4 val = make_float4(0.f, 0.f, 0.f, 0.f);
            if (row < nrows) {
                val = (gr < PASTLEN)
                    ? pv4[(size_t)(bh*PASTLEN + gr)*16 + c]
                    : gv4[(bh*QL + (gr - PASTLEN))*16 + c];
            }
            Vs4[f] = val;
        }

        // ---- phase A: scores (2 threads per kv row) ----
        float s[QL];
#pragma unroll
        for (int ii = 0; ii < QL; ii++) s[ii] = 0.f;
        const int j = c0 + rl;
        const bool valid = (rl < nrows);
        if (valid) {
            const float4* krow = (j < PASTLEN)
                ? pk4 + (size_t)(bh*PASTLEN + j)*16
                : gk4 + (size_t)(bh*QL + (j - PASTLEN))*16;
#pragma unroll
            for (int dbl = 0; dbl < 8; dbl++) {
                const int db = half*8 + dbl;
                const float4 k4 = krow[db];
#pragma unroll
                for (int ii = 0; ii < QL; ii++) {
                    const float4 q4 = qs4[ii*16 + db];
                    s[ii] += k4.x*q4.x + k4.y*q4.y + k4.z*q4.z + k4.w*q4.w;
                }
            }
        }
        float padadd = 0.f;
        if (valid && half == 0) padadd = padmask[b*TOTKV + j] * -1e9f;
#pragma unroll
        for (int ii = 0; ii < QL; ii++) {
            float stot = s[ii] + __shfl_xor_sync(0xffffffffu, s[ii], 1);
            if (half == 0) {
                if (!valid) stot = -1e30f;
                else {
                    stot += padadd;
                    if (j > PASTLEN + ii) stot -= 1e9f;
                }
                S[ii*CHUNK + rl] = stot;
            }
        }
        __syncthreads();

        // ---- phase B: online softmax + PV (16-lane group per query) ----
        float mx = -1e30f;
#pragma unroll
        for (int jj = 0; jj < CHUNK/16; jj++)
            mx = fmaxf(mx, S[i*CHUNK + dg + jj*16]);
        mx = fmaxf(mx, __shfl_xor_sync(0xffffffffu, mx, 8));
        mx = fmaxf(mx, __shfl_xor_sync(0xffffffffu, mx, 4));
        mx = fmaxf(mx, __shfl_xor_sync(0xffffffffu, mx, 2));
        mx = fmaxf(mx, __shfl_xor_sync(0xffffffffu, mx, 1));

        const float mnew = fmaxf(m, mx);
        const float corr = __expf(m - mnew);
        float lsum = 0.f;
#pragma unroll
        for (int jj = 0; jj < CHUNK/16; jj++) {
            const int idx = i*CHUNK + dg + jj*16;
            const float p = __expf(S[idx] - mnew);
            S[idx] = p;
            lsum += p;
        }
        __syncwarp();
        lsum += __shfl_xor_sync(0xffffffffu, lsum, 8);
        lsum += __shfl_xor_sync(0xffffffffu, lsum, 4);
        lsum += __shfl_xor_sync(0xffffffffu, lsum, 2);
        lsum += __shfl_xor_sync(0xffffffffu, lsum, 1);
        l = l * corr + lsum;
        m = mnew;
        acc.x *= corr; acc.y *= corr; acc.z *= corr; acc.w *= corr;

        const float4* S4 = (const float4*)(S + i*CHUNK);
#pragma unroll 8
        for (int j4 = 0; j4 < CHUNK/4; j4++) {
            const float4 p4 = S4[j4];
            const float4 v0 = Vs4[(j4*4 + 0)*16 + dg];
            const float4 v1 = Vs4[(j4*4 + 1)*16 + dg];
            const float4 v2 = Vs4[(j4*4 + 2)*16 + dg];
            const float4 v3 = Vs4[(j4*4 + 3)*16 + dg];
            acc.x += p4.x*v0.x + p4.y*v1.x + p4.z*v2.x + p4.w*v3.x;
            acc.y += p4.x*v0.y + p4.y*v1.y + p4.z*v2.y + p4.w*v3.y;
            acc.z += p4.x*v0.z + p4.y*v1.z + p4.z*v2.z + p4.w*v3.z;
            acc.w += p4.x*v0.w + p4.y*v1.w + p4.z*v2.w + p4.w*v3.w;
        }
    }

    // ---- write split partials ----
    const int pb = blockIdx.x;
    ((float4*)g_part_acc)[(pb*QL + i)*16 + dg] = acc;
    if (dg == 0) {
        g_part_m[pb*QL + i] = m;
        g_part_l[pb*QL + i] = l;
    }
}

// ============================================================
// Kernel 3: combine splits -> permuted mid layout.
// ============================================================
__global__ __launch_bounds__(256) void combine_kernel()
{
    const int bh = blockIdx.x;
    const int b = bh >> 4, h = bh & 15;
    const int t = threadIdx.x;
    const int i = t >> 4, dg = t & 15;

    float mg = -1e30f;
#pragma unroll
    for (int sp = 0; sp < NSPLIT; sp++)
        mg = fmaxf(mg, g_part_m[(bh*NSPLIT + sp)*QL + i]);

    float L = 0.f;
    float4 acc = make_float4(0.f, 0.f, 0.f, 0.f);
#pragma unroll
    for (int sp = 0; sp < NSPLIT; sp++) {
        const int pi = (bh*NSPLIT + sp)*QL + i;
        const float w = __expf(g_part_m[pi] - mg);
        L += g_part_l[pi] * w;
        const float4 a = ((const float4*)g_part_acc)[pi*16 + dg];
        acc.x += a.x * w; acc.y += a.y * w; acc.z += a.z * w; acc.w += a.w * w;
    }
    const float inv = 1.f / L;
    const float v[4] = {acc.x*inv, acc.y*inv, acc.z*inv, acc.w*inv};
#pragma unroll
    for (int k = 0; k < 4; k++) {
        const int d = dg*4 + k;
        g_mid[b*(QL*HID) + (d >> 2)*HID + (d & 3)*256 + i*16 + h] = v[k];
    }
}

// ============================================================
// Kernel 4a: output projection split-K partial. grid (16,2,KSPLIT).
// ============================================================
__global__ __launch_bounds__(256) void oproj_part_kernel(
    const float* __restrict__ Wo)
{
    __shared__ float As[64][17];
    __shared__ float Ws[64][17];

    const int tid = threadIdx.x;
    const int tx = tid & 15, ty = tid >> 4;
    const int col0 = blockIdx.x * 64;
    const int row0 = blockIdx.y * 64;
    const int ks   = blockIdx.z;

    float acc[4][4];
#pragma unroll
    for (int r = 0; r < 4; r++)
#pragma unroll
        for (int c = 0; c < 4; c++) acc[r][c] = 0.f;

    const int lr = tid >> 2;
    const int lk = (tid & 3) * 4;
    const float* Arow = g_mid + (size_t)(row0 + lr) * HID + ks*KSLICE + lk;
    const float* Wrow = Wo    + (size_t)(col0 + lr) * HID + ks*KSLICE + lk;

    float4 a4 = *(const float4*)Arow;
    float4 w4 = *(const float4*)Wrow;

    for (int t = 0; t < KSLICE/16; t++) {
        As[lr][lk] = a4.x; As[lr][lk+1] = a4.y; As[lr][lk+2] = a4.z; As[lr][lk+3] = a4.w;
        Ws[lr][lk] = w4.x; Ws[lr][lk+1] = w4.y; Ws[lr][lk+2] = w4.z; Ws[lr][lk+3] = w4.w;
        __syncthreads();
        if (t < KSLICE/16 - 1) {
            a4 = *(const float4*)(Arow + (t+1)*16);
            w4 = *(const float4*)(Wrow + (t+1)*16);
        }
#pragma unroll
        for (int kk = 0; kk < 16; kk++) {
            float av[4], wv[4];
#pragma unroll
            for (int r = 0; r < 4; r++) av[r] = As[ty*4 + r][kk];
#pragma unroll
            for (int c = 0; c < 4; c++) wv[c] = Ws[tx*4 + c][kk];
#pragma unroll
            for (int r = 0; r < 4; r++)
#pragma unroll
                for (int c = 0; c < 4; c++) acc[r][c] += av[r] * wv[c];
        }
        __syncthreads();
    }

#pragma unroll
    for (int r = 0; r < 4; r++) {
        const int m = row0 + ty*4 + r;
        float4 o = make_float4(acc[r][0], acc[r][1], acc[r][2], acc[r][3]);
        *(float4*)&g_op_pp[((size_t)ks*128 + m)*HID + col0 + tx*4] = o;
    }
}

// ============================================================
// Kernel 4b: reduce oproj partials + bias -> out. grid 128 x 256.
// ============================================================
__global__ __launch_bounds__(256) void oproj_reduce_kernel(
    const float* __restrict__ bo, float* __restrict__ out)
{
    const int idx = blockIdx.x * 256 + threadIdx.x;   // float4 idx, 0..32767
    const int m = idx >> 8;
    const int n = (idx & 255) * 4;
    const size_t base = (size_t)m*HID + n;

    float4 s = *(const float4*)&g_op_pp[base];
#pragma unroll
    for (int ks = 1; ks < KSPLIT; ks++) {
        float4 p = *(const float4*)&g_op_pp[(size_t)ks*128*HID + base];
        s.x += p.x; s.y += p.y; s.z += p.z; s.w += p.w;
    }
    s.x += bo[n]; s.y += bo[n+1]; s.z += bo[n+2]; s.w += bo[n+3];
    *(float4*)&out[base] = s;
}

// ============================================================
extern "C" void kernel_launch(void* const* d_in, const int* in_sizes, int n_in,
                              void* d_out, int out_size)
{
    const float* hidden  = (const float*)d_in[0];
    const float* past_k  = (const float*)d_in[1];
    const float* past_v  = (const float*)d_in[2];
    // d_in[3] causal_mask: computed analytically (j > PASTLEN + i)
    const float* padmask = (const float*)d_in[4];
    const float* Wq = (const float*)d_in[5];
    const float* bq = (const float*)d_in[6];
    const float* Wk = (const float*)d_in[7];
    const float* bk = (const float*)d_in[8];
    const float* Wv = (const float*)d_in[9];
    const float* bv = (const float*)d_in[10];
    const float* Wo = (const float*)d_in[11];
    const float* bo = (const float*)d_in[12];
    float* out = (float*)d_out;

    qkv_part_kernel<<<dim3(48, 2, KSPLIT), 256>>>(hidden, Wq, Wk, Wv);
    qkv_reduce_kernel<<<384, 256>>>(bq, bk, bv);
    attn_kernel<<<BB*NHAT*NSPLIT, 256>>>(past_k, past_v, padmask);
    combine_kernel<<<BB*NHAT, 256>>>();
    oproj_part_kernel<<<dim3(16, 2, KSPLIT), 256>>>(Wo);
    oproj_reduce_kernel<<<128, 256>>>(bo, out);
}

// round 9
// speedup vs baseline: 1.7559x; 1.4418x over previous
#include <cuda_runtime.h>
#include <cuda_bf16.h>
#include <cstdint>

// ---------------- problem constants ----------------
#define BB      8
#define QL      16
#define NHAT    16
#define HDIM    64
#define HID     1024
#define PASTLEN 8192
#define TOTKV   8208            // PASTLEN + QL
#define NSPLIT  16
#define SPLITBASE 512           // 8 chunks of 64; split 15 takes +16 tail
#define CHUNK2  64
#define NWARP   8
#define NPART   (NSPLIT*NWARP)  // 128 partials per bh
#define KSPLIT  4
#define KSLICE  (HID / KSPLIT)  // 256

// ---------------- device scratch (no allocation allowed) ----------------
__device__ float g_q  [BB*NHAT*QL*HDIM];                    // pre-scaled by 0.125
__device__ float g_k  [BB*NHAT*QL*HDIM];                    // new K rows
__device__ float g_v  [BB*NHAT*QL*HDIM];                    // new V rows
__device__ float g_qkv_pp[KSPLIT*128*3072];                 // qkv split-K partials
__device__ float g_op_pp [KSPLIT*128*HID];                  // oproj split-K partials
__device__ float g_part_acc[BB*NHAT*NPART*QL*HDIM];         // per-warp PV partials
__device__ float g_part_m  [BB*NHAT*NPART*QL];
__device__ float g_part_l  [BB*NHAT*NPART*QL];
__device__ float g_mid [BB*QL*HID];                         // permuted attn output

// ---------------- tf32 helpers ----------------
__device__ __forceinline__ uint32_t f2tf(float f) {
    uint32_t u;
    asm("cvt.rna.tf32.f32 %0, %1;" : "=r"(u) : "f"(f));
    return u;
}
__device__ __forceinline__ void mma_tf32(float& c0, float& c1, float& c2, float& c3,
    uint32_t a0, uint32_t a1, uint32_t a2, uint32_t a3, uint32_t b0, uint32_t b1)
{
    asm("mma.sync.aligned.m16n8k8.row.col.f32.tf32.tf32.f32 "
        "{%0,%1,%2,%3}, {%4,%5,%6,%7}, {%8,%9}, {%0,%1,%2,%3};"
        : "+f"(c0), "+f"(c1), "+f"(c2), "+f"(c3)
        : "r"(a0), "r"(a1), "r"(a2), "r"(a3), "r"(b0), "r"(b1));
}

// ============================================================
// Kernel 1a: fused QKV projection, split-K partial.
// ============================================================
__global__ __launch_bounds__(256) void qkv_part_kernel(
    const float* __restrict__ A,
    const float* __restrict__ Wq, const float* __restrict__ Wk,
    const float* __restrict__ Wv)
{
    __shared__ float As[64][17];
    __shared__ float Ws[64][17];

    const int tid = threadIdx.x;
    const int tx = tid & 15, ty = tid >> 4;
    const int col0 = blockIdx.x * 64;
    const int row0 = blockIdx.y * 64;
    const int ks   = blockIdx.z;
    const int mat  = col0 >> 10;
    const int f0   = col0 & 1023;
    const float* W = (mat == 0) ? Wq : (mat == 1) ? Wk : Wv;

    float acc[4][4];
#pragma unroll
    for (int r = 0; r < 4; r++)
#pragma unroll
        for (int c = 0; c < 4; c++) acc[r][c] = 0.f;

    const int lr = tid >> 2;
    const int lk = (tid & 3) * 4;
    const float* Arow = A + (size_t)(row0 + lr) * HID + ks*KSLICE + lk;
    const float* Wrow = W + (size_t)(f0  + lr) * HID + ks*KSLICE + lk;

    float4 a4 = *(const float4*)Arow;
    float4 w4 = *(const float4*)Wrow;

    for (int t = 0; t < KSLICE/16; t++) {
        As[lr][lk] = a4.x; As[lr][lk+1] = a4.y; As[lr][lk+2] = a4.z; As[lr][lk+3] = a4.w;
        Ws[lr][lk] = w4.x; Ws[lr][lk+1] = w4.y; Ws[lr][lk+2] = w4.z; Ws[lr][lk+3] = w4.w;
        __syncthreads();
        if (t < KSLICE/16 - 1) {
            a4 = *(const float4*)(Arow + (t+1)*16);
            w4 = *(const float4*)(Wrow + (t+1)*16);
        }
#pragma unroll
        for (int kk = 0; kk < 16; kk++) {
            float av[4], wv[4];
#pragma unroll
            for (int r = 0; r < 4; r++) av[r] = As[ty*4 + r][kk];
#pragma unroll
            for (int c = 0; c < 4; c++) wv[c] = Ws[tx*4 + c][kk];
#pragma unroll
            for (int r = 0; r < 4; r++)
#pragma unroll
                for (int c = 0; c < 4; c++) acc[r][c] += av[r] * wv[c];
        }
        __syncthreads();
    }

#pragma unroll
    for (int r = 0; r < 4; r++) {
        const int m = row0 + ty*4 + r;
        float4 o = make_float4(acc[r][0], acc[r][1], acc[r][2], acc[r][3]);
        *(float4*)&g_qkv_pp[((size_t)ks*128 + m)*3072 + col0 + tx*4] = o;
    }
}

// ============================================================
// Kernel 1b: reduce qkv split-K partials + bias -> [b][h][i][d]
// ============================================================
__global__ __launch_bounds__(256) void qkv_reduce_kernel(
    const float* __restrict__ bq, const float* __restrict__ bk,
    const float* __restrict__ bv)
{
    const int idx = blockIdx.x * 256 + threadIdx.x;
    const int m = idx / 768;
    const int f = (idx - m*768) * 4;
    const size_t base = (size_t)m*3072 + f;

    float4 s = *(const float4*)&g_qkv_pp[base];
#pragma unroll
    for (int ks = 1; ks < KSPLIT; ks++) {
        float4 p = *(const float4*)&g_qkv_pp[(size_t)ks*128*3072 + base];
        s.x += p.x; s.y += p.y; s.z += p.z; s.w += p.w;
    }

    const int mat = f >> 10;
    const int fl  = f & 1023;
    const float* bias = (mat == 0) ? bq : (mat == 1) ? bk : bv;
    s.x += bias[fl]; s.y += bias[fl+1]; s.z += bias[fl+2]; s.w += bias[fl+3];

    const int b = m >> 4, iq = m & 15;
    const int h = fl >> 6, d = fl & 63;
    const int dst = ((b*NHAT + h)*QL + iq)*HDIM + d;
    if (mat == 0) {
        s.x *= 0.125f; s.y *= 0.125f; s.z *= 0.125f; s.w *= 0.125f;
        *(float4*)&g_q[dst] = s;
    } else if (mat == 1) {
        *(float4*)&g_k[dst] = s;
    } else {
        *(float4*)&g_v[dst] = s;
    }
}

// ============================================================
// Kernel 2: flash attention, tf32 tensor-core, warp-local softmax.
// grid = BB*NHAT*NSPLIT, block = 256 (8 warps, each owns 8 KV rows/chunk).
// ============================================================
__global__ __launch_bounds__(256) void attn_mma_kernel(
    const float* __restrict__ past_k,
    const float* __restrict__ past_v,
    const float* __restrict__ padmask)
{
    __shared__ uint32_t Qs[QL][68];       // tf32 Q, pad->conflict-free a-frag LDS
    __shared__ uint32_t Ks[CHUNK2][68];   // tf32 K chunk
    __shared__ uint32_t Vs[CHUNK2][72];   // tf32 V chunk (72: conflict-free b-frag LDS)

    const int t    = threadIdx.x;
    const int lane = t & 31;
    const int w    = t >> 5;
    const int bh   = blockIdx.x >> 4;
    const int sp   = blockIdx.x & (NSPLIT - 1);
    const int b    = bh >> 4;
    const int s0   = sp * SPLITBASE;
    const int s1   = (sp == NSPLIT-1) ? TOTKV : s0 + SPLITBASE;

    const float4* pk4 = (const float4*)past_k;
    const float4* pv4 = (const float4*)past_v;
    const float4* gk4 = (const float4*)g_k;
    const float4* gv4 = (const float4*)g_v;

    // ---- stage Q (tf32) ----
    {
        float4 q4 = ((const float4*)g_q)[bh*256 + t];
        const int row = t >> 4, c = (t & 15) * 4;
        Qs[row][c]   = f2tf(q4.x);
        Qs[row][c+1] = f2tf(q4.y);
        Qs[row][c+2] = f2tf(q4.z);
        Qs[row][c+3] = f2tf(q4.w);
    }

    const int g   = lane >> 2;     // group id (query row base)
    const int tig = lane & 3;      // thread-in-group
    const int r0  = w * 8;         // this warp's kv-row base within chunk

    float m1 = -1e30f, m2 = -1e30f, l1 = 0.f, l2 = 0.f;
    float acc[8][4];
#pragma unroll
    for (int nt = 0; nt < 8; nt++)
#pragma unroll
        for (int c = 0; c < 4; c++) acc[nt][c] = 0.f;

    for (int c0 = s0; c0 < s1; c0 += CHUNK2) {
        const int nrows = min(CHUNK2, s1 - c0);
        __syncthreads();

        // ---- cooperative K/V load (coalesced), convert to tf32 ----
#pragma unroll
        for (int it = 0; it < 4; it++) {
            const int f = t + it*256;            // 0..1023
            const int row = f >> 4, cc = f & 15;
            const int gr = c0 + row;
            float4 kv = make_float4(0.f,0.f,0.f,0.f);
            float4 vv = make_float4(0.f,0.f,0.f,0.f);
            if (row < nrows) {
                if (gr < PASTLEN) {
                    kv = pk4[(size_t)(bh*PASTLEN + gr)*16 + cc];
                    vv = pv4[(size_t)(bh*PASTLEN + gr)*16 + cc];
                } else {
                    kv = gk4[(bh*QL + (gr - PASTLEN))*16 + cc];
                    vv = gv4[(bh*QL + (gr - PASTLEN))*16 + cc];
                }
            }
            const int c4 = cc * 4;
            Ks[row][c4]   = f2tf(kv.x); Ks[row][c4+1] = f2tf(kv.y);
            Ks[row][c4+2] = f2tf(kv.z); Ks[row][c4+3] = f2tf(kv.w);
            Vs[row][c4]   = f2tf(vv.x); Vs[row][c4+1] = f2tf(vv.y);
            Vs[row][c4+2] = f2tf(vv.z); Vs[row][c4+3] = f2tf(vv.w);
        }
        __syncthreads();

        // ---- scores: S_w(16q x 8kv) = Q x K_w^T ----
        float s0r = 0.f, s1r = 0.f, s2r = 0.f, s3r = 0.f;
#pragma unroll
        for (int kt = 0; kt < 8; kt++) {
            const int k0 = kt * 8;
            uint32_t a0 = Qs[g][k0 + tig];
            uint32_t a1 = Qs[g+8][k0 + tig];
            uint32_t a2 = Qs[g][k0 + tig + 4];
            uint32_t a3 = Qs[g+8][k0 + tig + 4];
            uint32_t b0 = Ks[r0 + g][k0 + tig];
            uint32_t b1 = Ks[r0 + g][k0 + tig + 4];
            mma_tf32(s0r, s1r, s2r, s3r, a0, a1, a2, a3, b0, b1);
        }

        // ---- masks ----
        const int jA = c0 + r0 + 2*tig;
        const int jB = jA + 1;
        const int iA = g, iB = g + 8;
        const bool vA = jA < s1, vB = jB < s1;
        const float pA = vA ? padmask[b*TOTKV + jA] * (-1e9f) : 0.f;
        const float pB = vB ? padmask[b*TOTKV + jB] * (-1e9f) : 0.f;
        s0r = vA ? s0r + pA + ((jA > PASTLEN + iA) ? -1e9f : 0.f) : -1e30f;
        s1r = vB ? s1r + pB + ((jB > PASTLEN + iA) ? -1e9f : 0.f) : -1e30f;
        s2r = vA ? s2r + pA + ((jA > PASTLEN + iB) ? -1e9f : 0.f) : -1e30f;
        s3r = vB ? s3r + pB + ((jB > PASTLEN + iB) ? -1e9f : 0.f) : -1e30f;

        // ---- per-warp online softmax (4-lane row groups) ----
        float mxA = fmaxf(s0r, s1r);
        float mxB = fmaxf(s2r, s3r);
        mxA = fmaxf(mxA, __shfl_xor_sync(0xffffffffu, mxA, 1));
        mxA = fmaxf(mxA, __shfl_xor_sync(0xffffffffu, mxA, 2));
        mxB = fmaxf(mxB, __shfl_xor_sync(0xffffffffu, mxB, 1));
        mxB = fmaxf(mxB, __shfl_xor_sync(0xffffffffu, mxB, 2));

        const float mn1 = fmaxf(m1, mxA);
        const float mn2 = fmaxf(m2, mxB);
        const float cor1 = __expf(m1 - mn1);
        const float cor2 = __expf(m2 - mn2);
        const float p0 = __expf(s0r - mn1);
        const float p1 = __expf(s1r - mn1);
        const float p2 = __expf(s2r - mn2);
        const float p3 = __expf(s3r - mn2);
        float ls1 = p0 + p1;
        float ls2 = p2 + p3;
        ls1 += __shfl_xor_sync(0xffffffffu, ls1, 1);
        ls1 += __shfl_xor_sync(0xffffffffu, ls1, 2);
        ls2 += __shfl_xor_sync(0xffffffffu, ls2, 1);
        ls2 += __shfl_xor_sync(0xffffffffu, ls2, 2);
        l1 = l1 * cor1 + ls1;  m1 = mn1;
        l2 = l2 * cor2 + ls2;  m2 = mn2;

#pragma unroll
        for (int nt = 0; nt < 8; nt++) {
            acc[nt][0] *= cor1; acc[nt][1] *= cor1;
            acc[nt][2] *= cor2; acc[nt][3] *= cor2;
        }

        // ---- P (C-frag) -> A-frag via shfl, cvt to tf32 ----
        const uint32_t u0 = f2tf(p0), u1 = f2tf(p1), u2 = f2tf(p2), u3 = f2tf(p3);
        const int src0 = (lane & ~3) | (tig >> 1);
        const int src2 = src0 + 2;
        const uint32_t x0 = __shfl_sync(0xffffffffu, u0, src0);
        const uint32_t x1 = __shfl_sync(0xffffffffu, u1, src0);
        const uint32_t y0 = __shfl_sync(0xffffffffu, u0, src2);
        const uint32_t y1 = __shfl_sync(0xffffffffu, u1, src2);
        const uint32_t z0 = __shfl_sync(0xffffffffu, u2, src0);
        const uint32_t z1 = __shfl_sync(0xffffffffu, u2, src2);
        const uint32_t q0 = __shfl_sync(0xffffffffu, u3, src0);
        const uint32_t q1 = __shfl_sync(0xffffffffu, u3, src2);
        const uint32_t pa0 = (tig & 1) ? x1 : x0;
        const uint32_t pa2 = (tig & 1) ? y1 : y0;
        const uint32_t pa1 = (tig & 1) ? q0 : z0;
        const uint32_t pa3 = (tig & 1) ? q1 : z1;

        // ---- PV: acc += P_w x V_w ----
#pragma unroll
        for (int nt = 0; nt < 8; nt++) {
            const int d0 = nt * 8;
            uint32_t b0 = Vs[r0 + tig][d0 + g];
            uint32_t b1 = Vs[r0 + tig + 4][d0 + g];
            mma_tf32(acc[nt][0], acc[nt][1], acc[nt][2], acc[nt][3],
                     pa0, pa1, pa2, pa3, b0, b1);
        }
    }

    // ---- write per-warp partials: [pb][q][d] ----
    const int pb = blockIdx.x * NWARP + w;   // (bh*NSPLIT+sp)*8 + w
#pragma unroll
    for (int nt = 0; nt < 8; nt++) {
        const int d = nt*8 + 2*tig;
        g_part_acc[((size_t)pb*QL + g)  *HDIM + d]     = acc[nt][0];
        g_part_acc[((size_t)pb*QL + g)  *HDIM + d + 1] = acc[nt][1];
        g_part_acc[((size_t)pb*QL + g+8)*HDIM + d]     = acc[nt][2];
        g_part_acc[((size_t)pb*QL + g+8)*HDIM + d + 1] = acc[nt][3];
    }
    if (tig == 0) {
        g_part_m[pb*QL + g]     = m1;
        g_part_m[pb*QL + g + 8] = m2;
        g_part_l[pb*QL + g]     = l1;
        g_part_l[pb*QL + g + 8] = l2;
    }
}

// ============================================================
// Kernel 3: combine 128 partials per bh -> permuted mid layout.
// ============================================================
__global__ __launch_bounds__(256) void combine_kernel()
{
    const int bh = blockIdx.x;
    const int b = bh >> 4, h = bh & 15;
    const int t = threadIdx.x;
    const int i = t >> 4, dg = t & 15;

    float mg = -1e30f;
#pragma unroll 8
    for (int p = 0; p < NPART; p++)
        mg = fmaxf(mg, g_part_m[(bh*NPART + p)*QL + i]);

    float L = 0.f;
    float4 acc = make_float4(0.f, 0.f, 0.f, 0.f);
#pragma unroll 4
    for (int p = 0; p < NPART; p++) {
        const int pi = (bh*NPART + p)*QL + i;
        const float wgt = __expf(g_part_m[pi] - mg);
        L += g_part_l[pi] * wgt;
        const float4 a = *(const float4*)&g_part_acc[(size_t)pi*HDIM + dg*4];
        acc.x += a.x * wgt; acc.y += a.y * wgt; acc.z += a.z * wgt; acc.w += a.w * wgt;
    }
    const float inv = 1.f / L;
    const float v[4] = {acc.x*inv, acc.y*inv, acc.z*inv, acc.w*inv};
#pragma unroll
    for (int k = 0; k < 4; k++) {
        const int d = dg*4 + k;
        g_mid[b*(QL*HID) + (d >> 2)*HID + (d & 3)*256 + i*16 + h] = v[k];
    }
}

// ============================================================
// Kernel 4a: output projection split-K partial.
// ============================================================
__global__ __launch_bounds__(256) void oproj_part_kernel(
    const float* __restrict__ Wo)
{
    __shared__ float As[64][17];
    __shared__ float Ws[64][17];

    const int tid = threadIdx.x;
    const int tx = tid & 15, ty = tid >> 4;
    const int col0 = blockIdx.x * 64;
    const int row0 = blockIdx.y * 64;
    const int ks   = blockIdx.z;

    float acc[4][4];
#pragma unroll
    for (int r = 0; r < 4; r++)
#pragma unroll
        for (int c = 0; c < 4; c++) acc[r][c] = 0.f;

    const int lr = tid >> 2;
    const int lk = (tid & 3) * 4;
    const float* Arow = g_mid + (size_t)(row0 + lr) * HID + ks*KSLICE + lk;
    const float* Wrow = Wo    + (size_t)(col0 + lr) * HID + ks*KSLICE + lk;

    float4 a4 = *(const float4*)Arow;
    float4 w4 = *(const float4*)Wrow;

    for (int t = 0; t < KSLICE/16; t++) {
        As[lr][lk] = a4.x; As[lr][lk+1] = a4.y; As[lr][lk+2] = a4.z; As[lr][lk+3] = a4.w;
        Ws[lr][lk] = w4.x; Ws[lr][lk+1] = w4.y; Ws[lr][lk+2] = w4.z; Ws[lr][lk+3] = w4.w;
        __syncthreads();
        if (t < KSLICE/16 - 1) {
            a4 = *(const float4*)(Arow + (t+1)*16);
            w4 = *(const float4*)(Wrow + (t+1)*16);
        }
#pragma unroll
        for (int kk = 0; kk < 16; kk++) {
            float av[4], wv[4];
#pragma unroll
            for (int r = 0; r < 4; r++) av[r] = As[ty*4 + r][kk];
#pragma unroll
            for (int c = 0; c < 4; c++) wv[c] = Ws[tx*4 + c][kk];
#pragma unroll
            for (int r = 0; r < 4; r++)
#pragma unroll
                for (int c = 0; c < 4; c++) acc[r][c] += av[r] * wv[c];
        }
        __syncthreads();
    }

#pragma unroll
    for (int r = 0; r < 4; r++) {
        const int m = row0 + ty*4 + r;
        float4 o = make_float4(acc[r][0], acc[r][1], acc[r][2], acc[r][3]);
        *(float4*)&g_op_pp[((size_t)ks*128 + m)*HID + col0 + tx*4] = o;
    }
}

// ============================================================
// Kernel 4b: reduce oproj partials + bias -> out.
// ============================================================
__global__ __launch_bounds__(256) void oproj_reduce_kernel(
    const float* __restrict__ bo, float* __restrict__ out)
{
    const int idx = blockIdx.x * 256 + threadIdx.x;
    const int m = idx >> 8;
    const int n = (idx & 255) * 4;
    const size_t base = (size_t)m*HID + n;

    float4 s = *(const float4*)&g_op_pp[base];
#pragma unroll
    for (int ks = 1; ks < KSPLIT; ks++) {
        float4 p = *(const float4*)&g_op_pp[(size_t)ks*128*HID + base];
        s.x += p.x; s.y += p.y; s.z += p.z; s.w += p.w;
    }
    s.x += bo[n]; s.y += bo[n+1]; s.z += bo[n+2]; s.w += bo[n+3];
    *(float4*)&out[base] = s;
}

// ============================================================
extern "C" void kernel_launch(void* const* d_in, const int* in_sizes, int n_in,
                              void* d_out, int out_size)
{
    const float* hidden  = (const float*)d_in[0];
    const float* past_k  = (const float*)d_in[1];
    const float* past_v  = (const float*)d_in[2];
    // d_in[3] causal_mask: computed analytically (j > PASTLEN + i)
    const float* padmask = (const float*)d_in[4];
    const float* Wq = (const float*)d_in[5];
    const float* bq = (const float*)d_in[6];
    const float* Wk = (const float*)d_in[7];
    const float* bk = (const float*)d_in[8];
    const float* Wv = (const float*)d_in[9];
    const float* bv = (const float*)d_in[10];
    const float* Wo = (const float*)d_in[11];
    const float* bo = (const float*)d_in[12];
    float* out = (float*)d_out;

    qkv_part_kernel<<<dim3(48, 2, KSPLIT), 256>>>(hidden, Wq, Wk, Wv);
    qkv_reduce_kernel<<<384, 256>>>(bq, bk, bv);
    attn_mma_kernel<<<BB*NHAT*NSPLIT, 256>>>(past_k, past_v, padmask);
    combine_kernel<<<BB*NHAT, 256>>>();
    oproj_part_kernel<<<dim3(16, 2, KSPLIT), 256>>>(Wo);
    oproj_reduce_kernel<<<128, 256>>>(bo, out);
}

// round 10
// speedup vs baseline: 2.8537x; 1.6252x over previous
#include <cuda_runtime.h>
#include <cuda_bf16.h>
#include <cstdint>

// ---------------- problem constants ----------------
#define BB      8
#define QL      16
#define NHAT    16
#define HDIM    64
#define HID     1024
#define PASTLEN 8192
#define TOTKV   8208            // PASTLEN + QL
#define NSPLIT  16
#define SPLITBASE 512           // 8 chunks of 64; split 15 takes +16 tail
#define CHUNK2  64
#define NWARP   8
#define KSPLIT  4
#define KSLICE  (HID / KSPLIT)  // 256

// ---------------- device scratch (no allocation allowed) ----------------
__device__ float g_q  [BB*NHAT*QL*HDIM];                    // pre-scaled by 0.125
__device__ float g_k  [BB*NHAT*QL*HDIM];                    // new K rows
__device__ float g_v  [BB*NHAT*QL*HDIM];                    // new V rows
__device__ float g_qkv_pp[KSPLIT*128*3072];                 // qkv split-K partials
__device__ float g_op_pp [KSPLIT*128*HID];                  // oproj split-K partials
__device__ float g_part_acc[BB*NHAT*NSPLIT*QL*HDIM];        // per-split PV partials
__device__ float g_part_m  [BB*NHAT*NSPLIT*QL];
__device__ float g_part_l  [BB*NHAT*NSPLIT*QL];
__device__ float g_mid [BB*QL*HID];                         // permuted attn output

// ---------------- tf32 helpers ----------------
__device__ __forceinline__ uint32_t f2tf(float f) {
    uint32_t u;
    asm("cvt.rna.tf32.f32 %0, %1;" : "=r"(u) : "f"(f));
    return u;
}
__device__ __forceinline__ void mma_tf32(float& c0, float& c1, float& c2, float& c3,
    uint32_t a0, uint32_t a1, uint32_t a2, uint32_t a3, uint32_t b0, uint32_t b1)
{
    asm("mma.sync.aligned.m16n8k8.row.col.f32.tf32.tf32.f32 "
        "{%0,%1,%2,%3}, {%4,%5,%6,%7}, {%8,%9}, {%0,%1,%2,%3};"
        : "+f"(c0), "+f"(c1), "+f"(c2), "+f"(c3)
        : "r"(a0), "r"(a1), "r"(a2), "r"(a3), "r"(b0), "r"(b1));
}

// ============================================================
// Kernel 1a: fused QKV projection, split-K partial.
// ============================================================
__global__ __launch_bounds__(256) void qkv_part_kernel(
    const float* __restrict__ A,
    const float* __restrict__ Wq, const float* __restrict__ Wk,
    const float* __restrict__ Wv)
{
    __shared__ float As[64][17];
    __shared__ float Ws[64][17];

    const int tid = threadIdx.x;
    const int tx = tid & 15, ty = tid >> 4;
    const int col0 = blockIdx.x * 64;
    const int row0 = blockIdx.y * 64;
    const int ks   = blockIdx.z;
    const int mat  = col0 >> 10;
    const int f0   = col0 & 1023;
    const float* W = (mat == 0) ? Wq : (mat == 1) ? Wk : Wv;

    float acc[4][4];
#pragma unroll
    for (int r = 0; r < 4; r++)
#pragma unroll
        for (int c = 0; c < 4; c++) acc[r][c] = 0.f;

    const int lr = tid >> 2;
    const int lk = (tid & 3) * 4;
    const float* Arow = A + (size_t)(row0 + lr) * HID + ks*KSLICE + lk;
    const float* Wrow = W + (size_t)(f0  + lr) * HID + ks*KSLICE + lk;

    float4 a4 = *(const float4*)Arow;
    float4 w4 = *(const float4*)Wrow;

    for (int t = 0; t < KSLICE/16; t++) {
        As[lr][lk] = a4.x; As[lr][lk+1] = a4.y; As[lr][lk+2] = a4.z; As[lr][lk+3] = a4.w;
        Ws[lr][lk] = w4.x; Ws[lr][lk+1] = w4.y; Ws[lr][lk+2] = w4.z; Ws[lr][lk+3] = w4.w;
        __syncthreads();
        if (t < KSLICE/16 - 1) {
            a4 = *(const float4*)(Arow + (t+1)*16);
            w4 = *(const float4*)(Wrow + (t+1)*16);
        }
#pragma unroll
        for (int kk = 0; kk < 16; kk++) {
            float av[4], wv[4];
#pragma unroll
            for (int r = 0; r < 4; r++) av[r] = As[ty*4 + r][kk];
#pragma unroll
            for (int c = 0; c < 4; c++) wv[c] = Ws[tx*4 + c][kk];
#pragma unroll
            for (int r = 0; r < 4; r++)
#pragma unroll
                for (int c = 0; c < 4; c++) acc[r][c] += av[r] * wv[c];
        }
        __syncthreads();
    }

#pragma unroll
    for (int r = 0; r < 4; r++) {
        const int m = row0 + ty*4 + r;
        float4 o = make_float4(acc[r][0], acc[r][1], acc[r][2], acc[r][3]);
        *(float4*)&g_qkv_pp[((size_t)ks*128 + m)*3072 + col0 + tx*4] = o;
    }
}

// ============================================================
// Kernel 1b: reduce qkv split-K partials + bias -> [b][h][i][d]
// ============================================================
__global__ __launch_bounds__(256) void qkv_reduce_kernel(
    const float* __restrict__ bq, const float* __restrict__ bk,
    const float* __restrict__ bv)
{
    const int idx = blockIdx.x * 256 + threadIdx.x;
    const int m = idx / 768;
    const int f = (idx - m*768) * 4;
    const size_t base = (size_t)m*3072 + f;

    float4 s = *(const float4*)&g_qkv_pp[base];
#pragma unroll
    for (int ks = 1; ks < KSPLIT; ks++) {
        float4 p = *(const float4*)&g_qkv_pp[(size_t)ks*128*3072 + base];
        s.x += p.x; s.y += p.y; s.z += p.z; s.w += p.w;
    }

    const int mat = f >> 10;
    const int fl  = f & 1023;
    const float* bias = (mat == 0) ? bq : (mat == 1) ? bk : bv;
    s.x += bias[fl]; s.y += bias[fl+1]; s.z += bias[fl+2]; s.w += bias[fl+3];

    const int b = m >> 4, iq = m & 15;
    const int h = fl >> 6, d = fl & 63;
    const int dst = ((b*NHAT + h)*QL + iq)*HDIM + d;
    if (mat == 0) {
        s.x *= 0.125f; s.y *= 0.125f; s.z *= 0.125f; s.w *= 0.125f;
        *(float4*)&g_q[dst] = s;
    } else if (mat == 1) {
        *(float4*)&g_k[dst] = s;
    } else {
        *(float4*)&g_v[dst] = s;
    }
}

// ============================================================
// Kernel 2: flash attention, tf32 MMA, register-prefetch pipeline,
// block-level partial merge. grid = BB*NHAT*NSPLIT, block = 256.
// ============================================================
__global__ __launch_bounds__(256) void attn_mma_kernel(
    const float* __restrict__ past_k,
    const float* __restrict__ past_v,
    const float* __restrict__ padmask)
{
    // one overlaid smem pool: Q/K/V tiles during mainloop,
    // merge buffers in the epilogue (after a syncthreads).
    __shared__ __align__(16) uint32_t SM[10048];          // 40.2 KB
    uint32_t (*Qs)[68] = (uint32_t(*)[68])(SM);           // [16][68]
    uint32_t (*Ks)[68] = (uint32_t(*)[68])(SM + 1088);    // [64][68]
    uint32_t (*Vs)[72] = (uint32_t(*)[72])(SM + 5440);    // [64][72]
    float* mrg_acc = (float*)SM;                          // [8][16][64]
    float* mrg_m   = (float*)(SM + 8192);                 // [8][16]
    float* mrg_l   = (float*)(SM + 8320);                 // [8][16]

    const int t    = threadIdx.x;
    const int lane = t & 31;
    const int w    = t >> 5;
    const int bh   = blockIdx.x >> 4;
    const int sp   = blockIdx.x & (NSPLIT - 1);
    const int b    = bh >> 4;
    const int s0   = sp * SPLITBASE;
    const int s1   = (sp == NSPLIT-1) ? TOTKV : s0 + SPLITBASE;

    const float4* pk4 = (const float4*)past_k;
    const float4* pv4 = (const float4*)past_v;
    const float4* gk4 = (const float4*)g_k;
    const float4* gv4 = (const float4*)g_v;

    // ---- stage Q (tf32) ----
    {
        float4 q4 = ((const float4*)g_q)[bh*256 + t];
        const int row = t >> 4, c = (t & 15) * 4;
        Qs[row][c]   = f2tf(q4.x);
        Qs[row][c+1] = f2tf(q4.y);
        Qs[row][c+2] = f2tf(q4.z);
        Qs[row][c+3] = f2tf(q4.w);
    }

    const int g   = lane >> 2;     // query row base
    const int tig = lane & 3;      // thread-in-group
    const int r0  = w * 8;         // this warp's kv-row base within chunk
    const int ldrow = t >> 4, ldc = t & 15;   // cooperative-load ids

    float m1 = -1e30f, m2 = -1e30f, l1 = 0.f, l2 = 0.f;
    float acc[8][4];
#pragma unroll
    for (int nt = 0; nt < 8; nt++)
#pragma unroll
        for (int c = 0; c < 4; c++) acc[nt][c] = 0.f;

    // ---- prefetch chunk 0 into registers ----
    float4 kr[4], vr[4];
    {
        const int nrows = min(CHUNK2, s1 - s0);
#pragma unroll
        for (int it = 0; it < 4; it++) {
            const int row = ldrow + it*16;
            const int gr = s0 + row;
            kr[it] = make_float4(0.f,0.f,0.f,0.f);
            vr[it] = make_float4(0.f,0.f,0.f,0.f);
            if (row < nrows) {
                if (gr < PASTLEN) {
                    kr[it] = pk4[(size_t)(bh*PASTLEN + gr)*16 + ldc];
                    vr[it] = pv4[(size_t)(bh*PASTLEN + gr)*16 + ldc];
                } else {
                    kr[it] = gk4[(bh*QL + (gr - PASTLEN))*16 + ldc];
                    vr[it] = gv4[(bh*QL + (gr - PASTLEN))*16 + ldc];
                }
            }
        }
    }

    for (int c0 = s0; c0 < s1; c0 += CHUNK2) {
        __syncthreads();   // previous compute done reading smem (also orders Q stage)

        // ---- store prefetched chunk to smem (tf32) ----
        const int c4 = ldc * 4;
#pragma unroll
        for (int it = 0; it < 4; it++) {
            const int row = ldrow + it*16;
            Ks[row][c4]   = f2tf(kr[it].x); Ks[row][c4+1] = f2tf(kr[it].y);
            Ks[row][c4+2] = f2tf(kr[it].z); Ks[row][c4+3] = f2tf(kr[it].w);
            Vs[row][c4]   = f2tf(vr[it].x); Vs[row][c4+1] = f2tf(vr[it].y);
            Vs[row][c4+2] = f2tf(vr[it].z); Vs[row][c4+3] = f2tf(vr[it].w);
        }
        __syncthreads();

        // ---- issue prefetch for next chunk (overlaps compute below) ----
        const int cn = c0 + CHUNK2;
        if (cn < s1) {
            const int nrows = min(CHUNK2, s1 - cn);
#pragma unroll
            for (int it = 0; it < 4; it++) {
                const int row = ldrow + it*16;
                const int gr = cn + row;
                kr[it] = make_float4(0.f,0.f,0.f,0.f);
                vr[it] = make_float4(0.f,0.f,0.f,0.f);
                if (row < nrows) {
                    if (gr < PASTLEN) {
                        kr[it] = pk4[(size_t)(bh*PASTLEN + gr)*16 + ldc];
                        vr[it] = pv4[(size_t)(bh*PASTLEN + gr)*16 + ldc];
                    } else {
                        kr[it] = gk4[(bh*QL + (gr - PASTLEN))*16 + ldc];
                        vr[it] = gv4[(bh*QL + (gr - PASTLEN))*16 + ldc];
                    }
                }
            }
        }

        // ---- scores: S_w(16q x 8kv) = Q x K_w^T ----
        float s0r = 0.f, s1r = 0.f, s2r = 0.f, s3r = 0.f;
#pragma unroll
        for (int kt = 0; kt < 8; kt++) {
            const int k0 = kt * 8;
            uint32_t a0 = Qs[g][k0 + tig];
            uint32_t a1 = Qs[g+8][k0 + tig];
            uint32_t a2 = Qs[g][k0 + tig + 4];
            uint32_t a3 = Qs[g+8][k0 + tig + 4];
            uint32_t b0 = Ks[r0 + g][k0 + tig];
            uint32_t b1 = Ks[r0 + g][k0 + tig + 4];
            mma_tf32(s0r, s1r, s2r, s3r, a0, a1, a2, a3, b0, b1);
        }

        // ---- masks ----
        const int jA = c0 + r0 + 2*tig;
        const int jB = jA + 1;
        const int iA = g, iB = g + 8;
        const bool vA = jA < s1, vB = jB < s1;
        const float pA = vA ? padmask[b*TOTKV + jA] * (-1e9f) : 0.f;
        const float pB = vB ? padmask[b*TOTKV + jB] * (-1e9f) : 0.f;
        s0r = vA ? s0r + pA + ((jA > PASTLEN + iA) ? -1e9f : 0.f) : -1e30f;
        s1r = vB ? s1r + pB + ((jB > PASTLEN + iA) ? -1e9f : 0.f) : -1e30f;
        s2r = vA ? s2r + pA + ((jA > PASTLEN + iB) ? -1e9f : 0.f) : -1e30f;
        s3r = vB ? s3r + pB + ((jB > PASTLEN + iB) ? -1e9f : 0.f) : -1e30f;

        // ---- per-warp online softmax (4-lane row groups) ----
        float mxA = fmaxf(s0r, s1r);
        float mxB = fmaxf(s2r, s3r);
        mxA = fmaxf(mxA, __shfl_xor_sync(0xffffffffu, mxA, 1));
        mxA = fmaxf(mxA, __shfl_xor_sync(0xffffffffu, mxA, 2));
        mxB = fmaxf(mxB, __shfl_xor_sync(0xffffffffu, mxB, 1));
        mxB = fmaxf(mxB, __shfl_xor_sync(0xffffffffu, mxB, 2));

        const float mn1 = fmaxf(m1, mxA);
        const float mn2 = fmaxf(m2, mxB);
        const float cor1 = __expf(m1 - mn1);
        const float cor2 = __expf(m2 - mn2);
        const float p0 = __expf(s0r - mn1);
        const float p1 = __expf(s1r - mn1);
        const float p2 = __expf(s2r - mn2);
        const float p3 = __expf(s3r - mn2);
        float ls1 = p0 + p1;
        float ls2 = p2 + p3;
        ls1 += __shfl_xor_sync(0xffffffffu, ls1, 1);
        ls1 += __shfl_xor_sync(0xffffffffu, ls1, 2);
        ls2 += __shfl_xor_sync(0xffffffffu, ls2, 1);
        ls2 += __shfl_xor_sync(0xffffffffu, ls2, 2);
        l1 = l1 * cor1 + ls1;  m1 = mn1;
        l2 = l2 * cor2 + ls2;  m2 = mn2;

#pragma unroll
        for (int nt = 0; nt < 8; nt++) {
            acc[nt][0] *= cor1; acc[nt][1] *= cor1;
            acc[nt][2] *= cor2; acc[nt][3] *= cor2;
        }

        // ---- P (C-frag) -> A-frag via shfl, cvt to tf32 ----
        const uint32_t u0 = f2tf(p0), u1 = f2tf(p1), u2 = f2tf(p2), u3 = f2tf(p3);
        const int src0 = (lane & ~3) | (tig >> 1);
        const int src2 = src0 + 2;
        const uint32_t x0 = __shfl_sync(0xffffffffu, u0, src0);
        const uint32_t x1 = __shfl_sync(0xffffffffu, u1, src0);
        const uint32_t y0 = __shfl_sync(0xffffffffu, u0, src2);
        const uint32_t y1 = __shfl_sync(0xffffffffu, u1, src2);
        const uint32_t z0 = __shfl_sync(0xffffffffu, u2, src0);
        const uint32_t z1 = __shfl_sync(0xffffffffu, u2, src2);
        const uint32_t q0 = __shfl_sync(0xffffffffu, u3, src0);
        const uint32_t q1 = __shfl_sync(0xffffffffu, u3, src2);
        const uint32_t pa0 = (tig & 1) ? x1 : x0;
        const uint32_t pa2 = (tig & 1) ? y1 : y0;
        const uint32_t pa1 = (tig & 1) ? q0 : z0;
        const uint32_t pa3 = (tig & 1) ? q1 : z1;

        // ---- PV: acc += P_w x V_w ----
#pragma unroll
        for (int nt = 0; nt < 8; nt++) {
            const int d0 = nt * 8;
            uint32_t b0 = Vs[r0 + tig][d0 + g];
            uint32_t b1 = Vs[r0 + tig + 4][d0 + g];
            mma_tf32(acc[nt][0], acc[nt][1], acc[nt][2], acc[nt][3],
                     pa0, pa1, pa2, pa3, b0, b1);
        }
    }

    // ================= block-level merge (smem overlay) =================
    __syncthreads();   // all warps done reading K/V/Q smem

#pragma unroll
    for (int nt = 0; nt < 8; nt++) {
        const int d = nt*8 + 2*tig;
        mrg_acc[(w*QL + g)  *HDIM + d]     = acc[nt][0];
        mrg_acc[(w*QL + g)  *HDIM + d + 1] = acc[nt][1];
        mrg_acc[(w*QL + g+8)*HDIM + d]     = acc[nt][2];
        mrg_acc[(w*QL + g+8)*HDIM + d + 1] = acc[nt][3];
    }
    if (tig == 0) {
        mrg_m[w*QL + g]     = m1;  mrg_m[w*QL + g + 8] = m2;
        mrg_l[w*QL + g]     = l1;  mrg_l[w*QL + g + 8] = l2;
    }
    __syncthreads();

    // thread t -> (q = t>>4, dg = t&15): merge 8 warps, write one float4
    {
        const int q = t >> 4, dg = t & 15;
        float mg = -1e30f;
#pragma unroll
        for (int ww = 0; ww < NWARP; ww++)
            mg = fmaxf(mg, mrg_m[ww*QL + q]);
        float L = 0.f;
        float4 a = make_float4(0.f, 0.f, 0.f, 0.f);
#pragma unroll
        for (int ww = 0; ww < NWARP; ww++) {
            const float wgt = __expf(mrg_m[ww*QL + q] - mg);
            L += mrg_l[ww*QL + q] * wgt;
            const float4 v = *(const float4*)&mrg_acc[(ww*QL + q)*HDIM + dg*4];
            a.x += v.x*wgt; a.y += v.y*wgt; a.z += v.z*wgt; a.w += v.w*wgt;
        }
        const int pb = blockIdx.x;               // bh*NSPLIT + sp
        *(float4*)&g_part_acc[((size_t)pb*QL + q)*HDIM + dg*4] = a;
        if (dg == 0) {
            g_part_m[pb*QL + q] = mg;
            g_part_l[pb*QL + q] = L;
        }
    }
}

// ============================================================
// Kernel 3: combine 16 split partials per bh -> permuted mid layout.
// ============================================================
__global__ __launch_bounds__(256) void combine_kernel()
{
    const int bh = blockIdx.x;
    const int b = bh >> 4, h = bh & 15;
    const int t = threadIdx.x;
    const int i = t >> 4, dg = t & 15;

    float mg = -1e30f;
#pragma unroll
    for (int sp = 0; sp < NSPLIT; sp++)
        mg = fmaxf(mg, g_part_m[(bh*NSPLIT + sp)*QL + i]);

    float L = 0.f;
    float4 acc = make_float4(0.f, 0.f, 0.f, 0.f);
#pragma unroll
    for (int sp = 0; sp < NSPLIT; sp++) {
        const int pi = (bh*NSPLIT + sp)*QL + i;
        const float wgt = __expf(g_part_m[pi] - mg);
        L += g_part_l[pi] * wgt;
        const float4 a = *(const float4*)&g_part_acc[(size_t)pi*HDIM + dg*4];
        acc.x += a.x * wgt; acc.y += a.y * wgt; acc.z += a.z * wgt; acc.w += a.w * wgt;
    }
    const float inv = 1.f / L;
    const float v[4] = {acc.x*inv, acc.y*inv, acc.z*inv, acc.w*inv};
#pragma unroll
    for (int k = 0; k < 4; k++) {
        const int d = dg*4 + k;
        g_mid[b*(QL*HID) + (d >> 2)*HID + (d & 3)*256 + i*16 + h] = v[k];
    }
}

// ============================================================
// Kernel 4a: output projection split-K partial.
// ============================================================
__global__ __launch_bounds__(256) void oproj_part_kernel(
    const float* __restrict__ Wo)
{
    __shared__ float As[64][17];
    __shared__ float Ws[64][17];

    const int tid = threadIdx.x;
    const int tx = tid & 15, ty = tid >> 4;
    const int col0 = blockIdx.x * 64;
    const int row0 = blockIdx.y * 64;
    const int ks   = blockIdx.z;

    float acc[4][4];
#pragma unroll
    for (int r = 0; r < 4; r++)
#pragma unroll
        for (int c = 0; c < 4; c++) acc[r][c] = 0.f;

    const int lr = tid >> 2;
    const int lk = (tid & 3) * 4;
    const float* Arow = g_mid + (size_t)(row0 + lr) * HID + ks*KSLICE + lk;
    const float* Wrow = Wo    + (size_t)(col0 + lr) * HID + ks*KSLICE + lk;

    float4 a4 = *(const float4*)Arow;
    float4 w4 = *(const float4*)Wrow;

    for (int t = 0; t < KSLICE/16; t++) {
        As[lr][lk] = a4.x; As[lr][lk+1] = a4.y; As[lr][lk+2] = a4.z; As[lr][lk+3] = a4.w;
        Ws[lr][lk] = w4.x; Ws[lr][lk+1] = w4.y; Ws[lr][lk+2] = w4.z; Ws[lr][lk+3] = w4.w;
        __syncthreads();
        if (t < KSLICE/16 - 1) {
            a4 = *(const float4*)(Arow + (t+1)*16);
            w4 = *(const float4*)(Wrow + (t+1)*16);
        }
#pragma unroll
        for (int kk = 0; kk < 16; kk++) {
            float av[4], wv[4];
#pragma unroll
            for (int r = 0; r < 4; r++) av[r] = As[ty*4 + r][kk];
#pragma unroll
            for (int c = 0; c < 4; c++) wv[c] = Ws[tx*4 + c][kk];
#pragma unroll
            for (int r = 0; r < 4; r++)
#pragma unroll
                for (int c = 0; c < 4; c++) acc[r][c] += av[r] * wv[c];
        }
        __syncthreads();
    }

#pragma unroll
    for (int r = 0; r < 4; r++) {
        const int m = row0 + ty*4 + r;
        float4 o = make_float4(acc[r][0], acc[r][1], acc[r][2], acc[r][3]);
        *(float4*)&g_op_pp[((size_t)ks*128 + m)*HID + col0 + tx*4] = o;
    }
}

// ============================================================
// Kernel 4b: reduce oproj partials + bias -> out.
// ============================================================
__global__ __launch_bounds__(256) void oproj_reduce_kernel(
    const float* __restrict__ bo, float* __restrict__ out)
{
    const int idx = blockIdx.x * 256 + threadIdx.x;
    const int m = idx >> 8;
    const int n = (idx & 255) * 4;
    const size_t base = (size_t)m*HID + n;

    float4 s = *(const float4*)&g_op_pp[base];
#pragma unroll
    for (int ks = 1; ks < KSPLIT; ks++) {
        float4 p = *(const float4*)&g_op_pp[(size_t)ks*128*HID + base];
        s.x += p.x; s.y += p.y; s.z += p.z; s.w += p.w;
    }
    s.x += bo[n]; s.y += bo[n+1]; s.z += bo[n+2]; s.w += bo[n+3];
    *(float4*)&out[base] = s;
}

// ============================================================
extern "C" void kernel_launch(void* const* d_in, const int* in_sizes, int n_in,
                              void* d_out, int out_size)
{
    const float* hidden  = (const float*)d_in[0];
    const float* past_k  = (const float*)d_in[1];
    const float* past_v  = (const float*)d_in[2];
    // d_in[3] causal_mask: computed analytically (j > PASTLEN + i)
    const float* padmask = (const float*)d_in[4];
    const float* Wq = (const float*)d_in[5];
    const float* bq = (const float*)d_in[6];
    const float* Wk = (const float*)d_in[7];
    const float* bk = (const float*)d_in[8];
    const float* Wv = (const float*)d_in[9];
    const float* bv = (const float*)d_in[10];
    const float* Wo = (const float*)d_in[11];
    const float* bo = (const float*)d_in[12];
    float* out = (float*)d_out;

    qkv_part_kernel<<<dim3(48, 2, KSPLIT), 256>>>(hidden, Wq, Wk, Wv);
    qkv_reduce_kernel<<<384, 256>>>(bq, bk, bv);
    attn_mma_kernel<<<BB*NHAT*NSPLIT, 256>>>(past_k, past_v, padmask);
    combine_kernel<<<BB*NHAT, 256>>>();
    oproj_part_kernel<<<dim3(16, 2, KSPLIT), 256>>>(Wo);
    oproj_reduce_kernel<<<128, 256>>>(bo, out);
}